// round 8
// baseline (speedup 1.0000x reference)
#include <cuda_runtime.h>

#define F_IN   10000
#define F_PAD  10240     // padded to 80 groups of 128 columns
#define NROWS  4096
#define GROUPS 80        // column groups of 128
#define C      4         // 32-col chunks per lane
#define WARPS  4         // warps per block (one group each)
#define RB     64        // rows per block
#define NPART  (GROUPS * 32)         // 2560 lane-partials per row
#define L2E    1.4426950408889634f
#define LN2    0.6931471805599453f
#define HL2PI2 1.3257480647361593f   // 0.5*log2(2*pi)

// scratch (no allocations allowed)
__device__ float g_pp[F_PAD * 9];               // per-column [m][{-K, B, C_}] base-2 Horner params
__device__ float g_part[(size_t)NROWS * NPART]; // per-row lane partials, row-major

__device__ __forceinline__ float ex2(float x) {
    float r; asm("ex2.approx.ftz.f32 %0, %1;" : "=f"(r) : "f"(x)); return r;
}
__device__ __forceinline__ float lg2(float x) {
    float r; asm("lg2.approx.ftz.f32 %0, %1;" : "=f"(r) : "f"(x)); return r;
}

// Empty kernels: shift the ncu capture window (-s 5 -c 1) onto spn_main.
__global__ void dummy_a_kernel() {}
__global__ void dummy_b_kernel() {}

// Kernel 1: one thread per (f, m). Folds w1 log-softmax, log(std), permutation
// into per-column base-2 Horner constants: t_m(x) = (-K x + B) x + C_.
// Pad columns contribute exactly 0: t0 = 0, t1 = t2 = -1e30.
__global__ void prep_kernel(const float* __restrict__ means,
                            const float* __restrict__ stds,
                            const float* __restrict__ w1,
                            const int*   __restrict__ idx) {
    int t = blockIdx.x * blockDim.x + threadIdx.x;
    int f = t / 3, m = t - f * 3;
    if (f >= F_PAD) return;
    if (f >= F_IN) {
        if (m == 0) {
            float* q = &g_pp[(size_t)f * 9];
            q[0]=0.f; q[1]=0.f; q[2]=0.f;
            q[3]=0.f; q[4]=0.f; q[5]=-1e30f;
            q[6]=0.f; q[7]=0.f; q[8]=-1e30f;
        }
        return;
    }
    float u0 = w1[f*3+0]*L2E, u1 = w1[f*3+1]*L2E, u2 = w1[f*3+2]*L2E;
    float mu = fmaxf(u0, fmaxf(u1, u2));
    float l2 = mu + lg2(ex2(u0-mu) + ex2(u1-mu) + ex2(u2-mu));  // log2 softmax denom
    float um   = (m == 0) ? u0 : (m == 1 ? u1 : u2);
    float mean = means[f*3+m];
    float sd   = stds[f*3+m];
    float K    = 0.7213475204444817f / (sd * sd);   // 0.5*log2(e)/sd^2
    float A    = (um - l2) - lg2(sd) - HL2PI2;
    float* q = &g_pp[(size_t)idx[f] * 9 + m * 3];
    q[0] = -K;
    q[1] = 2.0f * K * mean;
    q[2] = A - K * mean * mean;
}

// Kernel 2: warp owns 128 columns (lane = column within 4 chunks of 32),
// params in registers for the whole 64-row sweep, coalesced streaming LDG
// with 1-row prefetch (R5 structure). Per row each lane keeps (a = sum of mx,
// p = prod of (1+s)) over its 4 columns and stores its OWN partial
// v = a + lg2(p) — no butterfly, no SHFL chain, full-warp coalesced store.
__global__ __launch_bounds__(WARPS * 32) void spn_main(const float* __restrict__ x) {
    const int lane = threadIdx.x & 31;
    const int w    = threadIdx.x >> 5;
    const int g    = blockIdx.x * WARPS + w;      // column group 0..79
    const int r0   = blockIdx.y * RB;
    const int cbase = g * 128 + lane;

    float nk[C][3], pb[C][3], pc[C][3];
    #pragma unroll
    for (int c = 0; c < C; c++) {
        const float* p = &g_pp[(size_t)(cbase + c * 32) * 9];
        #pragma unroll
        for (int m = 0; m < 3; m++) {
            nk[c][m] = __ldg(p + m*3 + 0);
            pb[c][m] = __ldg(p + m*3 + 1);
            pc[c][m] = __ldg(p + m*3 + 2);
        }
    }
    bool inb[C];
    #pragma unroll
    for (int c = 0; c < C; c++) inb[c] = (cbase + c * 32) < F_IN;

    const float* xbase = x + (size_t)r0 * F_IN + g * 128 + lane;

    auto body = [&](int rval, const float (&xval)[C]) {
        float a = 0.0f, p = 1.0f;
        #pragma unroll
        for (int c = 0; c < C; c++) {
            float xv = xval[c];
            float t0 = fmaf(fmaf(xv, nk[c][0], pb[c][0]), xv, pc[c][0]);
            float t1 = fmaf(fmaf(xv, nk[c][1], pb[c][1]), xv, pc[c][1]);
            float t2 = fmaf(fmaf(xv, nk[c][2], pb[c][2]), xv, pc[c][2]);
            float hi = fmaxf(t0, t1), lo = fminf(t0, t1);
            float mx = fmaxf(hi, t2), md = fminf(hi, t2);
            float s  = ex2(md - mx) + ex2(lo - mx);
            a += mx;
            p = fmaf(s, p, p);     // p *= (1 + s);  p <= 3^4 = 81, no overflow
        }
        float v = a + lg2(p);     // lg2 is warp-wide MUFU regardless of lanes used
        g_part[(size_t)(r0 + rval) * NPART + g * 32 + lane] = v;
    };

    float nxt[C];
    #pragma unroll
    for (int c = 0; c < C; c++) nxt[c] = inb[c] ? __ldcs(xbase + c * 32) : 0.0f;

    #pragma unroll 2
    for (int r = 0; r < RB - 1; r++) {
        float cur[C];
        #pragma unroll
        for (int c = 0; c < C; c++) cur[c] = nxt[c];
        const float* xq = xbase + (size_t)(r + 1) * F_IN;
        #pragma unroll
        for (int c = 0; c < C; c++) nxt[c] = inb[c] ? __ldcs(xq + c * 32) : 0.0f;
        body(r, cur);
    }
    body(RB - 1, nxt);
}

// Kernel 3: fold 2560 lane-partials per row (one warp per row, coalesced).
__global__ void reduce_kernel(float* __restrict__ out) {
    const int lane = threadIdx.x & 31;
    const int n    = blockIdx.x * (blockDim.x >> 5) + (threadIdx.x >> 5);
    if (n >= NROWS) return;
    const float* p = &g_part[(size_t)n * NPART];
    float s = 0.0f;
    #pragma unroll 8
    for (int i = 0; i < NPART / 32; i++) s += p[lane + i * 32];
    #pragma unroll
    for (int off = 16; off; off >>= 1)
        s += __shfl_xor_sync(0xffffffffu, s, off);
    if (lane == 0) out[n] = s * LN2;
}

extern "C" void kernel_launch(void* const* d_in, const int* in_sizes, int n_in,
                              void* d_out, int out_size) {
    const float* x     = (const float*)d_in[0];
    const float* means = (const float*)d_in[1];
    const float* stds  = (const float*)d_in[2];
    const float* w1    = (const float*)d_in[3];
    // d_in[4..7] = w2..w5: provably no-ops (log_softmax over size-1 axis == 0)
    const int*   idx   = (const int*)d_in[8];

    prep_kernel<<<(F_PAD * 3 + 127) / 128, 128>>>(means, stds, w1, idx);
    dummy_a_kernel<<<1, 32>>>();   // ncu -s 5 alignment: put spn_main at slot 6
    dummy_b_kernel<<<1, 32>>>();
    spn_main<<<dim3(GROUPS / WARPS, NROWS / RB), WARPS * 32>>>(x);
    reduce_kernel<<<NROWS / 8, 256>>>((float*)d_out);
}

// round 9
// speedup vs baseline: 1.0342x; 1.0342x over previous
#include <cuda_runtime.h>

#define F_IN   10000
#define F_PAD  10240     // padded to 160 groups of 64 columns
#define NROWS  4096
#define GROUPS 160       // column groups of 64
#define C      2         // 32-col chunks per lane (2*32 = 64 cols per warp)
#define WARPS  4         // warps per block (one group each)
#define RB     64        // rows per block
#define NPART  (GROUPS * 8)          // 1280 partials per row
#define L2E    1.4426950408889634f
#define LN2    0.6931471805599453f
#define HL2PI2 1.3257480647361593f   // 0.5*log2(2*pi)

// scratch (no allocations allowed)
__device__ float g_pp[F_PAD * 9];               // per-column [m][{-K, B, C_}] base-2 Horner params
__device__ float g_part[(size_t)NROWS * NPART]; // per-row partials, row-major

__device__ __forceinline__ float ex2(float x) {
    float r; asm("ex2.approx.ftz.f32 %0, %1;" : "=f"(r) : "f"(x)); return r;
}
__device__ __forceinline__ float lg2(float x) {
    float r; asm("lg2.approx.ftz.f32 %0, %1;" : "=f"(r) : "f"(x)); return r;
}

// Empty kernels: keep the ncu capture window (-s 5 -c 1) on spn_main.
__global__ void dummy_a_kernel() {}
__global__ void dummy_b_kernel() {}

// Kernel 1: one thread per (f, m). Folds w1 log-softmax, log(std), permutation
// into per-column base-2 Horner constants: t_m(x) = (-K x + B) x + C_.
// Pad columns contribute exactly 0: t0 = 0, t1 = t2 = -1e30.
__global__ void prep_kernel(const float* __restrict__ means,
                            const float* __restrict__ stds,
                            const float* __restrict__ w1,
                            const int*   __restrict__ idx) {
    int t = blockIdx.x * blockDim.x + threadIdx.x;
    int f = t / 3, m = t - f * 3;
    if (f >= F_PAD) return;
    if (f >= F_IN) {
        if (m == 0) {
            float* q = &g_pp[(size_t)f * 9];
            q[0]=0.f; q[1]=0.f; q[2]=0.f;
            q[3]=0.f; q[4]=0.f; q[5]=-1e30f;
            q[6]=0.f; q[7]=0.f; q[8]=-1e30f;
        }
        return;
    }
    float u0 = w1[f*3+0]*L2E, u1 = w1[f*3+1]*L2E, u2 = w1[f*3+2]*L2E;
    float mu = fmaxf(u0, fmaxf(u1, u2));
    float l2 = mu + lg2(ex2(u0-mu) + ex2(u1-mu) + ex2(u2-mu));  // log2 softmax denom
    float um   = (m == 0) ? u0 : (m == 1 ? u1 : u2);
    float mean = means[f*3+m];
    float sd   = stds[f*3+m];
    float K    = 0.7213475204444817f / (sd * sd);   // 0.5*log2(e)/sd^2
    float A    = (um - l2) - lg2(sd) - HL2PI2;
    float* q = &g_pp[(size_t)idx[f] * 9 + m * 3];
    q[0] = -K;
    q[1] = 2.0f * K * mean;
    q[2] = A - K * mean * mean;
}

// Kernel 2: warp owns 64 columns (lane = column within 2 chunks of 32); only
// 18 param registers per thread -> high occupancy (latency-bound per R8 ncu:
// occ 46%, all pipes <31%). 1-row prefetch, per-lane (a, p) accumulation,
// 2-step butterfly, ONE lg2, lanes 0-7 store 8 partials.
__global__ __launch_bounds__(WARPS * 32) void spn_main(const float* __restrict__ x) {
    const int lane = threadIdx.x & 31;
    const int w    = threadIdx.x >> 5;
    const int g    = blockIdx.x * WARPS + w;      // column group 0..159
    const int r0   = blockIdx.y * RB;
    const int cbase = g * 64 + lane;

    float nk[C][3], pb[C][3], pc[C][3];
    #pragma unroll
    for (int c = 0; c < C; c++) {
        const float* p = &g_pp[(size_t)(cbase + c * 32) * 9];
        #pragma unroll
        for (int m = 0; m < 3; m++) {
            nk[c][m] = __ldg(p + m*3 + 0);
            pb[c][m] = __ldg(p + m*3 + 1);
            pc[c][m] = __ldg(p + m*3 + 2);
        }
    }
    bool inb[C];
    #pragma unroll
    for (int c = 0; c < C; c++) inb[c] = (cbase + c * 32) < F_IN;

    const float* xbase = x + (size_t)r0 * F_IN + g * 64 + lane;

    auto body = [&](int rval, const float (&xval)[C]) {
        float a = 0.0f, p = 1.0f;
        #pragma unroll
        for (int c = 0; c < C; c++) {
            float xv = xval[c];
            float t0 = fmaf(fmaf(xv, nk[c][0], pb[c][0]), xv, pc[c][0]);
            float t1 = fmaf(fmaf(xv, nk[c][1], pb[c][1]), xv, pc[c][1]);
            float t2 = fmaf(fmaf(xv, nk[c][2], pb[c][2]), xv, pc[c][2]);
            float hi = fmaxf(t0, t1), lo = fminf(t0, t1);
            float mx = fmaxf(hi, t2), md = fminf(hi, t2);
            float s  = ex2(md - mx) + ex2(lo - mx);
            a += mx;
            p = fmaf(s, p, p);     // p *= (1 + s)
        }
        a += __shfl_xor_sync(0xffffffffu, a, 16);
        p *= __shfl_xor_sync(0xffffffffu, p, 16);
        a += __shfl_xor_sync(0xffffffffu, a, 8);
        p *= __shfl_xor_sync(0xffffffffu, p, 8);
        float v = a + lg2(p);      // p <= 3^8 = 6561, no overflow
        if (lane < 8)
            g_part[(size_t)(r0 + rval) * NPART + g * 8 + lane] = v;
    };

    float nxt[C];
    #pragma unroll
    for (int c = 0; c < C; c++) nxt[c] = inb[c] ? __ldcs(xbase + c * 32) : 0.0f;

    #pragma unroll 2
    for (int r = 0; r < RB - 1; r++) {
        float cur[C];
        #pragma unroll
        for (int c = 0; c < C; c++) cur[c] = nxt[c];
        const float* xq = xbase + (size_t)(r + 1) * F_IN;
        #pragma unroll
        for (int c = 0; c < C; c++) nxt[c] = inb[c] ? __ldcs(xq + c * 32) : 0.0f;
        body(r, cur);
    }
    body(RB - 1, nxt);
}

// Kernel 3: fold 1280 partials per row (one warp per row, coalesced).
__global__ void reduce_kernel(float* __restrict__ out) {
    const int lane = threadIdx.x & 31;
    const int n    = blockIdx.x * (blockDim.x >> 5) + (threadIdx.x >> 5);
    if (n >= NROWS) return;
    const float* p = &g_part[(size_t)n * NPART];
    float s = 0.0f;
    #pragma unroll 8
    for (int i = 0; i < NPART / 32; i++) s += p[lane + i * 32];
    #pragma unroll
    for (int off = 16; off; off >>= 1)
        s += __shfl_xor_sync(0xffffffffu, s, off);
    if (lane == 0) out[n] = s * LN2;
}

extern "C" void kernel_launch(void* const* d_in, const int* in_sizes, int n_in,
                              void* d_out, int out_size) {
    const float* x     = (const float*)d_in[0];
    const float* means = (const float*)d_in[1];
    const float* stds  = (const float*)d_in[2];
    const float* w1    = (const float*)d_in[3];
    // d_in[4..7] = w2..w5: provably no-ops (log_softmax over size-1 axis == 0)
    const int*   idx   = (const int*)d_in[8];

    prep_kernel<<<(F_PAD * 3 + 127) / 128, 128>>>(means, stds, w1, idx);
    dummy_a_kernel<<<1, 32>>>();   // ncu -s 5 alignment: spn_main at slot 6
    dummy_b_kernel<<<1, 32>>>();
    spn_main<<<dim3(GROUPS / WARPS, NROWS / RB), WARPS * 32>>>(x);
    reduce_kernel<<<NROWS / 8, 256>>>((float*)d_out);
}

// round 10
// speedup vs baseline: 1.3057x; 1.2624x over previous
#include <cuda_runtime.h>
#include <cuda_pipeline.h>

#define F_IN   10000
#define F_PAD  10240     // padded to 80 groups of 128 columns
#define NROWS  4096
#define GROUPS 80        // column groups of 128
#define WARPS  4         // warps per block (one group each)
#define RB     64        // rows per block
#define D      4         // cp.async row-slot ring depth per warp
#define NPART  (GROUPS * 8)          // 640 partials per row
#define L2E    1.4426950408889634f
#define LN2    0.6931471805599453f
#define HL2PI2 1.3257480647361593f   // 0.5*log2(2*pi)

// scratch (no allocations allowed)
__device__ float g_pp[F_PAD * 9];               // per-column [m][{-K, B, C_}] base-2 Horner params
__device__ float g_part[(size_t)NROWS * NPART]; // per-row partials, row-major

__device__ __forceinline__ float ex2(float x) {
    float r; asm("ex2.approx.ftz.f32 %0, %1;" : "=f"(r) : "f"(x)); return r;
}
__device__ __forceinline__ float lg2(float x) {
    float r; asm("lg2.approx.ftz.f32 %0, %1;" : "=f"(r) : "f"(x)); return r;
}

// Empty kernels: keep the ncu capture window (-s 5 -c 1) on spn_main.
__global__ void dummy_a_kernel() {}
__global__ void dummy_b_kernel() {}

// Kernel 1: one thread per (f, m). Folds w1 log-softmax, log(std), permutation
// into per-column base-2 Horner constants: t_m(x) = (-K x + B) x + C_.
// Pad columns contribute exactly 0: t0 = 0, t1 = t2 = -1e30.
__global__ void prep_kernel(const float* __restrict__ means,
                            const float* __restrict__ stds,
                            const float* __restrict__ w1,
                            const int*   __restrict__ idx) {
    int t = blockIdx.x * blockDim.x + threadIdx.x;
    int f = t / 3, m = t - f * 3;
    if (f >= F_PAD) return;
    if (f >= F_IN) {
        if (m == 0) {
            float* q = &g_pp[(size_t)f * 9];
            q[0]=0.f; q[1]=0.f; q[2]=0.f;
            q[3]=0.f; q[4]=0.f; q[5]=-1e30f;
            q[6]=0.f; q[7]=0.f; q[8]=-1e30f;
        }
        return;
    }
    float u0 = w1[f*3+0]*L2E, u1 = w1[f*3+1]*L2E, u2 = w1[f*3+2]*L2E;
    float mu = fmaxf(u0, fmaxf(u1, u2));
    float l2 = mu + lg2(ex2(u0-mu) + ex2(u1-mu) + ex2(u2-mu));  // log2 softmax denom
    float um   = (m == 0) ? u0 : (m == 1 ? u1 : u2);
    float mean = means[f*3+m];
    float sd   = stds[f*3+m];
    float K    = 0.7213475204444817f / (sd * sd);   // 0.5*log2(e)/sd^2
    float A    = (um - l2) - lg2(sd) - HL2PI2;
    float* q = &g_pp[(size_t)idx[f] * 9 + m * 3];
    q[0] = -K;
    q[1] = 2.0f * K * mean;
    q[2] = A - K * mean * mean;
}

// Kernel 2: warp owns 128 consecutive columns; lane owns 4 consecutive columns.
// x rows are staged via cp.async (LDGSTS) into a D-deep per-warp SMEM ring —
// loads never hold registers and never block until wait_prior, so DRAM latency
// is hidden even at moderate occupancy (R8/R9 ncu: latency-bound, all pipes
// <31%). Each lane copies and consumes ONLY its own 16B -> no block syncs.
// Per row: per-lane (a = sum mx, p = prod(1+s)); 2-step butterfly, ONE lg2,
// lanes 0-7 store 8 partials (R5's proven epilogue).
__global__ __launch_bounds__(WARPS * 32) void spn_main(const float* __restrict__ x) {
    const int lane = threadIdx.x & 31;
    const int w    = threadIdx.x >> 5;
    const int g    = blockIdx.x * WARPS + w;      // column group 0..79
    const int r0   = blockIdx.y * RB;
    const int cbase = g * 128 + lane * 4;         // 4 consecutive columns

    __shared__ float4 buf[WARPS][D][32];          // per-warp row-slot ring

    float nk[4][3], pb[4][3], pc[4][3];
    #pragma unroll
    for (int c = 0; c < 4; c++) {
        const float* p = &g_pp[(size_t)(cbase + c) * 9];
        #pragma unroll
        for (int m = 0; m < 3; m++) {
            nk[c][m] = __ldg(p + m*3 + 0);
            pb[c][m] = __ldg(p + m*3 + 1);
            pc[c][m] = __ldg(p + m*3 + 2);
        }
    }
    // 10000 % 4 == 0 -> a lane's float4 is entirely in- or out-of-bounds.
    const bool inb = cbase < F_IN;
    // OOB lanes: their slots are never written by cp.async; park zeros there
    // once so the body computes on finite values (pad params give 0 anyway).
    if (!inb) {
        #pragma unroll
        for (int s = 0; s < D; s++) buf[w][s][lane] = make_float4(0.f,0.f,0.f,0.f);
    }

    const float* gsrc = x + (size_t)r0 * F_IN + g * 128 + lane * 4;

    auto body = [&](int rval, float4 xv4) {
        const float xa[4] = {xv4.x, xv4.y, xv4.z, xv4.w};
        float a = 0.0f, p = 1.0f;
        #pragma unroll
        for (int c = 0; c < 4; c++) {
            float xv = xa[c];
            float t0 = fmaf(fmaf(xv, nk[c][0], pb[c][0]), xv, pc[c][0]);
            float t1 = fmaf(fmaf(xv, nk[c][1], pb[c][1]), xv, pc[c][1]);
            float t2 = fmaf(fmaf(xv, nk[c][2], pb[c][2]), xv, pc[c][2]);
            float hi = fmaxf(t0, t1), lo = fminf(t0, t1);
            float mx = fmaxf(hi, t2), md = fminf(hi, t2);
            float s  = ex2(md - mx) + ex2(lo - mx);
            a += mx;
            p = fmaf(s, p, p);     // p *= (1 + s)
        }
        a += __shfl_xor_sync(0xffffffffu, a, 16);
        p *= __shfl_xor_sync(0xffffffffu, p, 16);
        a += __shfl_xor_sync(0xffffffffu, a, 8);
        p *= __shfl_xor_sync(0xffffffffu, p, 8);
        float v = a + lg2(p);      // p <= 3^16, no overflow
        if (lane < 8)
            g_part[(size_t)(r0 + rval) * NPART + g * 8 + lane] = v;
    };

    // Prologue: D-1 copies in flight (rows 0..D-2).
    #pragma unroll
    for (int i = 0; i < D - 1; i++) {
        if (inb) __pipeline_memcpy_async(&buf[w][i][lane], gsrc + (size_t)i * F_IN, 16);
        __pipeline_commit();
    }

    for (int r = 0; r < RB; r++) {
        int rn = r + D - 1;
        if (inb && rn < RB)
            __pipeline_memcpy_async(&buf[w][rn % D][lane], gsrc + (size_t)rn * F_IN, 16);
        __pipeline_commit();            // empty group past the end keeps counts aligned
        __pipeline_wait_prior(D - 2);   // row r's copy (issued D-1 commits ago) done
        float4 xv4 = buf[w][r % D][lane];
        body(r, xv4);
    }
}

// Kernel 3: fold 640 partials per row (one warp per row, deterministic order).
__global__ void reduce_kernel(float* __restrict__ out) {
    const int lane = threadIdx.x & 31;
    const int n    = blockIdx.x * (blockDim.x >> 5) + (threadIdx.x >> 5);
    if (n >= NROWS) return;
    const float* p = &g_part[(size_t)n * NPART];
    float s = 0.0f;
    #pragma unroll
    for (int i = 0; i < NPART / 32; i++) s += p[lane + i * 32];
    #pragma unroll
    for (int off = 16; off; off >>= 1)
        s += __shfl_xor_sync(0xffffffffu, s, off);
    if (lane == 0) out[n] = s * LN2;
}

extern "C" void kernel_launch(void* const* d_in, const int* in_sizes, int n_in,
                              void* d_out, int out_size) {
    const float* x     = (const float*)d_in[0];
    const float* means = (const float*)d_in[1];
    const float* stds  = (const float*)d_in[2];
    const float* w1    = (const float*)d_in[3];
    // d_in[4..7] = w2..w5: provably no-ops (log_softmax over size-1 axis == 0)
    const int*   idx   = (const int*)d_in[8];

    prep_kernel<<<(F_PAD * 3 + 127) / 128, 128>>>(means, stds, w1, idx);
    dummy_a_kernel<<<1, 32>>>();   // ncu -s 5 alignment: spn_main at slot 6
    dummy_b_kernel<<<1, 32>>>();
    spn_main<<<dim3(GROUPS / WARPS, NROWS / RB), WARPS * 32>>>(x);
    reduce_kernel<<<NROWS / 8, 256>>>((float*)d_out);
}

// round 12
// speedup vs baseline: 1.4238x; 1.0905x over previous
#include <cuda_runtime.h>
#include <cuda_pipeline.h>

#define F_IN   10000
#define F_PAD  10240     // padded to 80 groups of 128 columns
#define NROWS  4096
#define GROUPS 80        // column groups of 128
#define WARPS  4         // warps per block (one group each)
#define RB     64        // rows per block
#define CH     4         // rows per cp.async chunk (double-buffered)
#define NC     (RB / CH) // chunks per block
#define NPART  (GROUPS * 8)          // 640 partials per row
#define L2E    1.4426950408889634f
#define LN2    0.6931471805599453f
#define HL2PI2 1.3257480647361593f   // 0.5*log2(2*pi)

// scratch (no allocations allowed)
__device__ float g_pp[F_PAD * 9];               // per-column [m][{-K, B, C_}] base-2 Horner params
__device__ float g_part[(size_t)NROWS * NPART]; // per-row partials, row-major

__device__ __forceinline__ float ex2(float x) {
    float r; asm("ex2.approx.ftz.f32 %0, %1;" : "=f"(r) : "f"(x)); return r;
}
__device__ __forceinline__ float lg2(float x) {
    float r; asm("lg2.approx.ftz.f32 %0, %1;" : "=f"(r) : "f"(x)); return r;
}

// Empty kernels: keep the ncu capture window (-s 5 -c 1) on spn_main.
__global__ void dummy_a_kernel() {}
__global__ void dummy_b_kernel() {}

// Kernel 1: one thread per (f, m). Folds w1 log-softmax, log(std), permutation
// into per-column base-2 Horner constants: t_m(x) = (-K x + B) x + C_.
// Pad columns contribute exactly 0: t0 = 0, t1 = t2 = -1e30 (so garbage x is
// harmless there — enables unpredicated clamped loads in the main kernel).
__global__ void prep_kernel(const float* __restrict__ means,
                            const float* __restrict__ stds,
                            const float* __restrict__ w1,
                            const int*   __restrict__ idx) {
    int t = blockIdx.x * blockDim.x + threadIdx.x;
    int f = t / 3, m = t - f * 3;
    if (f >= F_PAD) return;
    if (f >= F_IN) {
        if (m == 0) {
            float* q = &g_pp[(size_t)f * 9];
            q[0]=0.f; q[1]=0.f; q[2]=0.f;
            q[3]=0.f; q[4]=0.f; q[5]=-1e30f;
            q[6]=0.f; q[7]=0.f; q[8]=-1e30f;
        }
        return;
    }
    float u0 = w1[f*3+0]*L2E, u1 = w1[f*3+1]*L2E, u2 = w1[f*3+2]*L2E;
    float mu = fmaxf(u0, fmaxf(u1, u2));
    float l2 = mu + lg2(ex2(u0-mu) + ex2(u1-mu) + ex2(u2-mu));  // log2 softmax denom
    float um   = (m == 0) ? u0 : (m == 1 ? u1 : u2);
    float mean = means[f*3+m];
    float sd   = stds[f*3+m];
    float K    = 0.7213475204444817f / (sd * sd);   // 0.5*log2(e)/sd^2
    float A    = (um - l2) - lg2(sd) - HL2PI2;
    float* q = &g_pp[(size_t)idx[f] * 9 + m * 3];
    q[0] = -K;
    q[1] = 2.0f * K * mean;
    q[2] = A - K * mean * mean;
}

// Kernel 2: warp owns 128 consecutive columns; lane owns 4 consecutive columns.
// x rows are staged via cp.async into a double-buffered 4-row chunk per warp:
// ONE commit/wait per 4 rows, compile-time slot indices, one pointer bump per
// chunk (R10 ncu: alu 35.7% — pipeline bookkeeping was a first-order cost).
// 4 independent row-chains per chunk give intra-warp ILP. OOB lanes load a
// clamped in-bounds address (pad params zero their contribution) — no
// predication anywhere. Per row: (a = sum mx, p = prod(1+s)); 2-step
// butterfly, ONE lg2, lanes 0-7 store 8 partials.
__global__ __launch_bounds__(WARPS * 32) void spn_main(const float* __restrict__ x) {
    const int lane = threadIdx.x & 31;
    const int w    = threadIdx.x >> 5;
    const int g    = blockIdx.x * WARPS + w;      // column group 0..79
    const int r0   = blockIdx.y * RB;
    const int cbase = g * 128 + lane * 4;         // 4 consecutive columns

    __shared__ float4 buf[WARPS][2][CH][32];      // per-warp double-buffered chunks

    float nk[4][3], pb[4][3], pc[4][3];
    #pragma unroll
    for (int c = 0; c < 4; c++) {
        const float* p = &g_pp[(size_t)(cbase + c) * 9];
        #pragma unroll
        for (int m = 0; m < 3; m++) {
            nk[c][m] = __ldg(p + m*3 + 0);
            pb[c][m] = __ldg(p + m*3 + 1);
            pc[c][m] = __ldg(p + m*3 + 2);
        }
    }
    // Clamp OOB lanes (cbase >= F_IN) to a valid address; their params are the
    // pad params, which make the contribution exactly 0 regardless of x.
    const int ccl = (cbase < F_IN) ? cbase : (F_IN - 4);
    const float* gsrc = x + (size_t)r0 * F_IN + ccl;

    auto body = [&](int rval, float4 xv4) {
        const float xa[4] = {xv4.x, xv4.y, xv4.z, xv4.w};
        float a = 0.0f, p = 1.0f;
        #pragma unroll
        for (int c = 0; c < 4; c++) {
            float xv = xa[c];
            float t0 = fmaf(fmaf(xv, nk[c][0], pb[c][0]), xv, pc[c][0]);
            float t1 = fmaf(fmaf(xv, nk[c][1], pb[c][1]), xv, pc[c][1]);
            float t2 = fmaf(fmaf(xv, nk[c][2], pb[c][2]), xv, pc[c][2]);
            float hi = fmaxf(t0, t1), lo = fminf(t0, t1);
            float mx = fmaxf(hi, t2), md = fminf(hi, t2);
            float s  = ex2(md - mx) + ex2(lo - mx);
            a += mx;
            p = fmaf(s, p, p);     // p *= (1 + s)
        }
        a += __shfl_xor_sync(0xffffffffu, a, 16);
        p *= __shfl_xor_sync(0xffffffffu, p, 16);
        a += __shfl_xor_sync(0xffffffffu, a, 8);
        p *= __shfl_xor_sync(0xffffffffu, p, 8);
        float v = a + lg2(p);      // p <= 3^16, no overflow
        if (lane < 8)
            g_part[(size_t)(r0 + rval) * NPART + g * 8 + lane] = v;
    };

    // Prologue: chunk 0 in flight.
    #pragma unroll
    for (int i = 0; i < CH; i++)
        __pipeline_memcpy_async(&buf[w][0][i][lane], gsrc + (size_t)i * F_IN, 16);
    __pipeline_commit();

    const float* gp = gsrc + (size_t)CH * F_IN;   // next chunk's base

    for (int k = 0; k < NC; k++) {
        const int b = k & 1;
        if (k + 1 < NC) {
            #pragma unroll
            for (int i = 0; i < CH; i++)
                __pipeline_memcpy_async(&buf[w][b ^ 1][i][lane], gp + (size_t)i * F_IN, 16);
            gp += (size_t)CH * F_IN;
        }
        __pipeline_commit();
        __pipeline_wait_prior(1);      // chunk k complete
        #pragma unroll
        for (int i = 0; i < CH; i++)
            body(k * CH + i, buf[w][b][i][lane]);
    }
}

// Kernel 3: fold 640 partials per row (one warp per row, deterministic order).
__global__ void reduce_kernel(float* __restrict__ out) {
    const int lane = threadIdx.x & 31;
    const int n    = blockIdx.x * (blockDim.x >> 5) + (threadIdx.x >> 5);
    if (n >= NROWS) return;
    const float* p = &g_part[(size_t)n * NPART];
    float s = 0.0f;
    #pragma unroll
    for (int i = 0; i < NPART / 32; i++) s += p[lane + i * 32];
    #pragma unroll
    for (int off = 16; off; off >>= 1)
        s += __shfl_xor_sync(0xffffffffu, s, off);
    if (lane == 0) out[n] = s * LN2;
}

extern "C" void kernel_launch(void* const* d_in, const int* in_sizes, int n_in,
                              void* d_out, int out_size) {
    const float* x     = (const float*)d_in[0];
    const float* means = (const float*)d_in[1];
    const float* stds  = (const float*)d_in[2];
    const float* w1    = (const float*)d_in[3];
    // d_in[4..7] = w2..w5: provably no-ops (log_softmax over size-1 axis == 0)
    const int*   idx   = (const int*)d_in[8];

    prep_kernel<<<(F_PAD * 3 + 127) / 128, 128>>>(means, stds, w1, idx);
    dummy_a_kernel<<<1, 32>>>();   // ncu -s 5 alignment: spn_main at slot 6
    dummy_b_kernel<<<1, 32>>>();
    spn_main<<<dim3(GROUPS / WARPS, NROWS / RB), WARPS * 32>>>(x);
    reduce_kernel<<<NROWS / 8, 256>>>((float*)d_out);
}

// round 13
// speedup vs baseline: 1.6744x; 1.1760x over previous
#include <cuda_runtime.h>
#include <cuda_pipeline.h>

#define F_IN   10000
#define F_PAD  10240     // padded to 80 groups of 128 columns
#define NROWS  4096
#define GROUPS 80        // column groups of 128
#define WARPS  4         // warps per block (one group each)
#define RB     64        // rows per block
#define CH     4         // rows per cp.async chunk (double-buffered)
#define NC     (RB / CH) // chunks per block (16)
#define NPART  (GROUPS * 8)          // 640 partials per row
#define L2E    1.4426950408889634f
#define LN2    0.6931471805599453f
#define HL2PI2 1.3257480647361593f   // 0.5*log2(2*pi)

// scratch (no allocations allowed)
__device__ float g_pp[F_PAD * 9];               // per-column [m][{-K, B, C_}] base-2 Horner params
__device__ float g_part[(size_t)NROWS * NPART]; // per-row partials, row-major

__device__ __forceinline__ float ex2(float x) {
    float r; asm("ex2.approx.ftz.f32 %0, %1;" : "=f"(r) : "f"(x)); return r;
}
__device__ __forceinline__ float lg2(float x) {
    float r; asm("lg2.approx.ftz.f32 %0, %1;" : "=f"(r) : "f"(x)); return r;
}

// Empty kernels: keep the ncu capture window (-s 5 -c 1) on spn_main.
__global__ void dummy_a_kernel() {}
__global__ void dummy_b_kernel() {}

// Kernel 1: one thread per (f, m). Folds w1 log-softmax, log(std), permutation
// into per-column base-2 Horner constants: t_m(x) = (-K x + B) x + C_.
// Pad columns contribute exactly 0: t0 = 0, t1 = t2 = -1e30 (garbage x is
// harmless there — enables unpredicated clamped loads in the main kernel).
__global__ void prep_kernel(const float* __restrict__ means,
                            const float* __restrict__ stds,
                            const float* __restrict__ w1,
                            const int*   __restrict__ idx) {
    int t = blockIdx.x * blockDim.x + threadIdx.x;
    int f = t / 3, m = t - f * 3;
    if (f >= F_PAD) return;
    if (f >= F_IN) {
        if (m == 0) {
            float* q = &g_pp[(size_t)f * 9];
            q[0]=0.f; q[1]=0.f; q[2]=0.f;
            q[3]=0.f; q[4]=0.f; q[5]=-1e30f;
            q[6]=0.f; q[7]=0.f; q[8]=-1e30f;
        }
        return;
    }
    float u0 = w1[f*3+0]*L2E, u1 = w1[f*3+1]*L2E, u2 = w1[f*3+2]*L2E;
    float mu = fmaxf(u0, fmaxf(u1, u2));
    float l2 = mu + lg2(ex2(u0-mu) + ex2(u1-mu) + ex2(u2-mu));  // log2 softmax denom
    float um   = (m == 0) ? u0 : (m == 1 ? u1 : u2);
    float mean = means[f*3+m];
    float sd   = stds[f*3+m];
    float K    = 0.7213475204444817f / (sd * sd);   // 0.5*log2(e)/sd^2
    float A    = (um - l2) - lg2(sd) - HL2PI2;
    float* q = &g_pp[(size_t)idx[f] * 9 + m * 3];
    q[0] = -K;
    q[1] = 2.0f * K * mean;
    q[2] = A - K * mean * mean;
}

// Kernel 2: warp owns 128 consecutive columns; lane owns 4 consecutive columns.
// cp.async double-buffered 4-row chunks, with the R12 profile's addressing tax
// stripped (alu was 32.6%, ~113 issue slots/warp-row vs ~60 algorithmic):
//  - chunk loop manually unrolled x2 -> buffer selector is COMPILE-TIME, all
//    LDS/LDGSTS addresses are [hoisted_base + imm]
//  - g_part written through a hoisted pointer bumped by NPART per row (no
//    per-row 64-bit IMAD.WIDE chain)
// Per row: (a = sum mx, p = prod(1+s)); 2-step butterfly, ONE lg2, lanes 0-7
// store 8 partials.
__global__ __launch_bounds__(WARPS * 32) void spn_main(const float* __restrict__ x) {
    const int lane = threadIdx.x & 31;
    const int w    = threadIdx.x >> 5;
    const int g    = blockIdx.x * WARPS + w;      // column group 0..79
    const int r0   = blockIdx.y * RB;
    const int cbase = g * 128 + lane * 4;         // 4 consecutive columns

    __shared__ float4 buf[WARPS][2][CH][32];      // per-warp double-buffered chunks

    float nk[4][3], pb[4][3], pc[4][3];
    #pragma unroll
    for (int c = 0; c < 4; c++) {
        const float* p = &g_pp[(size_t)(cbase + c) * 9];
        #pragma unroll
        for (int m = 0; m < 3; m++) {
            nk[c][m] = __ldg(p + m*3 + 0);
            pb[c][m] = __ldg(p + m*3 + 1);
            pc[c][m] = __ldg(p + m*3 + 2);
        }
    }
    // Clamp OOB lanes to a valid address; pad params zero their contribution.
    const int ccl = (cbase < F_IN) ? cbase : (F_IN - 4);
    const float* gp = x + (size_t)r0 * F_IN + ccl;

    float4* s0 = &buf[w][0][0][lane];   // row stride = 32 float4s, imm offsets
    float4* s1 = &buf[w][1][0][lane];

    float* outp = g_part + (size_t)r0 * NPART + g * 8 + lane;
    const bool wr = (lane < 8);

    auto body = [&](float4 xv4) {
        const float xa[4] = {xv4.x, xv4.y, xv4.z, xv4.w};
        float a = 0.0f, p = 1.0f;
        #pragma unroll
        for (int c = 0; c < 4; c++) {
            float xv = xa[c];
            float t0 = fmaf(fmaf(xv, nk[c][0], pb[c][0]), xv, pc[c][0]);
            float t1 = fmaf(fmaf(xv, nk[c][1], pb[c][1]), xv, pc[c][1]);
            float t2 = fmaf(fmaf(xv, nk[c][2], pb[c][2]), xv, pc[c][2]);
            float hi = fmaxf(t0, t1), lo = fminf(t0, t1);
            float mx = fmaxf(hi, t2), md = fminf(hi, t2);
            float s  = ex2(md - mx) + ex2(lo - mx);
            a += mx;
            p = fmaf(s, p, p);     // p *= (1 + s)
        }
        a += __shfl_xor_sync(0xffffffffu, a, 16);
        p *= __shfl_xor_sync(0xffffffffu, p, 16);
        a += __shfl_xor_sync(0xffffffffu, a, 8);
        p *= __shfl_xor_sync(0xffffffffu, p, 8);
        float v = a + lg2(p);      // p <= 3^16, no overflow
        if (wr) *outp = v;
        outp += NPART;
    };

    // Prologue: chunk 0 -> buffer 0.
    #pragma unroll
    for (int i = 0; i < CH; i++)
        __pipeline_memcpy_async(s0 + i * 32, gp + (size_t)i * F_IN, 16);
    __pipeline_commit();
    gp += (size_t)CH * F_IN;

    #pragma unroll 1
    for (int k = 0; k < NC; k += 2) {
        // Issue chunk k+1 -> buffer 1 (always exists: NC even).
        #pragma unroll
        for (int i = 0; i < CH; i++)
            __pipeline_memcpy_async(s1 + i * 32, gp + (size_t)i * F_IN, 16);
        gp += (size_t)CH * F_IN;
        __pipeline_commit();
        __pipeline_wait_prior(1);       // chunk k ready in buffer 0
        #pragma unroll
        for (int i = 0; i < CH; i++) body(s0[i * 32]);

        // Issue chunk k+2 -> buffer 0 (if it exists).
        if (k + 2 < NC) {
            #pragma unroll
            for (int i = 0; i < CH; i++)
                __pipeline_memcpy_async(s0 + i * 32, gp + (size_t)i * F_IN, 16);
            gp += (size_t)CH * F_IN;
        }
        __pipeline_commit();            // (possibly empty group keeps counts aligned)
        __pipeline_wait_prior(1);       // chunk k+1 ready in buffer 1
        #pragma unroll
        for (int i = 0; i < CH; i++) body(s1[i * 32]);
    }
}

// Kernel 3: fold 640 partials per row (one warp per row, deterministic order).
__global__ void reduce_kernel(float* __restrict__ out) {
    const int lane = threadIdx.x & 31;
    const int n    = blockIdx.x * (blockDim.x >> 5) + (threadIdx.x >> 5);
    if (n >= NROWS) return;
    const float* p = &g_part[(size_t)n * NPART];
    float s = 0.0f;
    #pragma unroll
    for (int i = 0; i < NPART / 32; i++) s += p[lane + i * 32];
    #pragma unroll
    for (int off = 16; off; off >>= 1)
        s += __shfl_xor_sync(0xffffffffu, s, off);
    if (lane == 0) out[n] = s * LN2;
}

extern "C" void kernel_launch(void* const* d_in, const int* in_sizes, int n_in,
                              void* d_out, int out_size) {
    const float* x     = (const float*)d_in[0];
    const float* means = (const float*)d_in[1];
    const float* stds  = (const float*)d_in[2];
    const float* w1    = (const float*)d_in[3];
    // d_in[4..7] = w2..w5: provably no-ops (log_softmax over size-1 axis == 0)
    const int*   idx   = (const int*)d_in[8];

    prep_kernel<<<(F_PAD * 3 + 127) / 128, 128>>>(means, stds, w1, idx);
    dummy_a_kernel<<<1, 32>>>();   // ncu -s 5 alignment: spn_main at slot 6
    dummy_b_kernel<<<1, 32>>>();
    spn_main<<<dim3(GROUPS / WARPS, NROWS / RB), WARPS * 32>>>(x);
    reduce_kernel<<<NROWS / 8, 256>>>((float*)d_out);
}